// round 6
// baseline (speedup 1.0000x reference)
#include <cuda_runtime.h>
#include <cstdint>
#include <cmath>

#define T_SEQ   4096
#define TAGS    24
#define START_T 22
#define STOP_T  23
#define NEGV    (-10000.0f)

#define NCTA_DIR    64
#define REC_THREADS 256

// ---------------- scratch (device globals; no cudaMalloc allowed) ----------
__device__ float    g_xg[(size_t)T_SEQ * 4096];   // [t][dir*2048 + gate*512 + cell]
__device__ float    g_lstm[(size_t)T_SEQ * 1024]; // [t][dir*512 + cell]
__device__ float    g_feats[T_SEQ * TAGS];
__device__ float    g_h[2][2][512];               // [dir][parity][cell]
__device__ unsigned g_barC[2];
__device__ unsigned g_barG[2];

// ---------------- kernel 1: fused gather + input-projection GEMM -----------
// out[m][n] = emb[sent[m]] . W[n] + bias[n], M=N=4096, K=512
__global__ void proj_gemm(const int* __restrict__ sent, const float* __restrict__ emb,
                          const float* __restrict__ wf, const float* __restrict__ wb,
                          const float* __restrict__ bihf, const float* __restrict__ bhhf,
                          const float* __restrict__ bihb, const float* __restrict__ bhhb)
{
    __shared__ __align__(16) float As[32][68];
    __shared__ __align__(16) float Bs[32][68];
    __shared__ int toks[64];

    const int tid = threadIdx.x;          // 0..255
    const int m0 = blockIdx.y * 64;
    const int n0 = blockIdx.x * 64;
    if (tid < 64) toks[tid] = sent[m0 + tid];
    __syncthreads();

    const int ty = tid >> 4;              // 0..15 (m groups of 4)
    const int tx = tid & 15;              // 0..15 (n groups of 4)

    float acc[4][4];
#pragma unroll
    for (int i = 0; i < 4; i++)
#pragma unroll
        for (int j = 0; j < 4; j++) acc[i][j] = 0.f;

    for (int k0 = 0; k0 < 512; k0 += 32) {
#pragma unroll
        for (int r = 0; r < 2; r++) {
            int idx = tid + r * 256;      // 0..511
            int row = idx >> 3;           // 0..63
            int kq  = idx & 7;            // 0..7 (float4 within 32 k's)
            float4 a = *(const float4*)(emb + (size_t)toks[row] * 512 + k0 + kq * 4);
            As[kq*4+0][row] = a.x; As[kq*4+1][row] = a.y;
            As[kq*4+2][row] = a.z; As[kq*4+3][row] = a.w;
            int n = n0 + row;
            const float* wsrc = (n < 2048) ? (wf + (size_t)n * 512)
                                           : (wb + (size_t)(n - 2048) * 512);
            float4 b = *(const float4*)(wsrc + k0 + kq * 4);
            Bs[kq*4+0][row] = b.x; Bs[kq*4+1][row] = b.y;
            Bs[kq*4+2][row] = b.z; Bs[kq*4+3][row] = b.w;
        }
        __syncthreads();
#pragma unroll
        for (int kk = 0; kk < 32; kk++) {
            float4 aa = *(const float4*)&As[kk][ty * 4];
            float4 bb = *(const float4*)&Bs[kk][tx * 4];
            float av[4] = {aa.x, aa.y, aa.z, aa.w};
            float bv[4] = {bb.x, bb.y, bb.z, bb.w};
#pragma unroll
            for (int i = 0; i < 4; i++)
#pragma unroll
                for (int j = 0; j < 4; j++) acc[i][j] += av[i] * bv[j];
        }
        __syncthreads();
    }

#pragma unroll
    for (int i = 0; i < 4; i++) {
        int m = m0 + ty * 4 + i;
        float* orow = g_xg + (size_t)m * 4096 + n0 + tx * 4;
#pragma unroll
        for (int j = 0; j < 4; j++) {
            int n = n0 + tx * 4 + j;
            float bias = (n < 2048) ? (bihf[n] + bhhf[n])
                                    : (bihb[n - 2048] + bhhb[n - 2048]);
            orow[j] = acc[i][j] + bias;
        }
    }
}

// ---------------- kernel 2: persistent BiLSTM recurrence -------------------
__device__ __forceinline__ void dir_barrier(int d)
{
    __syncthreads();
    if (threadIdx.x == 0) {
        __threadfence();
        volatile unsigned* vg = &g_barG[d];
        unsigned g = *vg;
        unsigned a = atomicAdd(&g_barC[d], 1u);
        if (a == NCTA_DIR - 1) {
            g_barC[d] = 0;
            __threadfence();
            atomicAdd(&g_barG[d], 1u);
        } else {
            while (*vg == g) __nanosleep(32);
        }
        __threadfence();
    }
    __syncthreads();
}

__global__ void __launch_bounds__(REC_THREADS, 1)
lstm_rec(const float* __restrict__ whf, const float* __restrict__ whb,
         const float* __restrict__ h0, const float* __restrict__ c0)
{
    const int cta = blockIdx.x;       // 0..127
    const int d   = cta >> 6;         // direction
    const int r   = cta & 63;         // CTA within direction: owns cells [8r,8r+8)
    const int tid = threadIdx.x;      // 0..255
    const int lr  = tid >> 3;         // 0..31 local gate-row
    const int kp  = tid & 7;          // 0..7  k-slice (64 k each)
    const int gate = lr >> 3;
    const int cell = (r << 3) + (lr & 7);
    const int row  = gate * 512 + cell;

    const float* whh = d ? whb : whf;
    const float4* __restrict__ wrow =
        (const float4*)(whh + (size_t)row * 512 + kp * 64);

    __shared__ __align__(16) float hbuf[8 * 68]; // padded: kp*68 segments
    __shared__ float sg[32];

    float cst = 0.f;
    if (tid < 8) cst = c0[d * 512 + (r << 3) + tid];
    if (r == 0)
        for (int j = tid; j < 512; j += REC_THREADS)
            g_h[d][0][j] = h0[d * 512 + j];

    dir_barrier(d);

    const float4* hv = (const float4*)(hbuf + kp * 68);

    for (int s = 0; s < T_SEQ; s++) {
        const int t  = d ? (T_SEQ - 1 - s) : s;
        const int rb = s & 1;

        for (int j = tid; j < 512; j += REC_THREADS)
            hbuf[(j >> 6) * 68 + (j & 63)] = g_h[d][rb][j];
        __syncthreads();

        float4 acc = {0.f, 0.f, 0.f, 0.f};
#pragma unroll
        for (int i = 0; i < 16; i++) {
            float4 w = wrow[i];
            float4 h = hv[i];
            acc.x += w.x * h.x; acc.y += w.y * h.y;
            acc.z += w.z * h.z; acc.w += w.w * h.w;
        }
        float a = (acc.x + acc.y) + (acc.z + acc.w);
        a += __shfl_xor_sync(0xffffffffu, a, 1);
        a += __shfl_xor_sync(0xffffffffu, a, 2);
        a += __shfl_xor_sync(0xffffffffu, a, 4);
        if (kp == 0)
            sg[lr] = a + g_xg[(size_t)t * 4096 + d * 2048 + row];
        __syncthreads();

        if (tid < 8) {
            float iv = sg[tid], fg = sg[8 + tid], gv = sg[16 + tid], ov = sg[24 + tid];
            iv = 1.f / (1.f + expf(-iv));
            fg = 1.f / (1.f + expf(-fg));
            gv = tanhf(gv);
            ov = 1.f / (1.f + expf(-ov));
            cst = fg * cst + iv * gv;
            float hn = ov * tanhf(cst);
            g_h[d][rb ^ 1][(r << 3) + tid] = hn;
            g_lstm[(size_t)t * 1024 + d * 512 + (r << 3) + tid] = hn;
        }
        dir_barrier(d);
    }
}

// ---------------- kernel 3: tag features -----------------------------------
__global__ void feats_k(const float* __restrict__ wtag, const float* __restrict__ btag)
{
    const int t = blockIdx.x;
    const int w = threadIdx.x >> 5;   // 8 warps
    const int lane = threadIdx.x & 31;

    const float4* lx = (const float4*)(g_lstm + (size_t)t * 1024 + lane * 32);
    float4 X[8];
#pragma unroll
    for (int i = 0; i < 8; i++) X[i] = lx[i];

#pragma unroll
    for (int rep = 0; rep < 3; rep++) {
        int tag = w + rep * 8;        // 0..23
        const float4* wt = (const float4*)(wtag + (size_t)tag * 1024 + lane * 32);
        float a = 0.f;
#pragma unroll
        for (int i = 0; i < 8; i++) {
            float4 v = wt[i];
            a += X[i].x * v.x + X[i].y * v.y + X[i].z * v.z + X[i].w * v.w;
        }
#pragma unroll
        for (int o = 16; o; o >>= 1) a += __shfl_xor_sync(0xffffffffu, a, o);
        if (lane == 0) g_feats[t * TAGS + tag] = a + btag[tag];
    }
}

// ---------------- kernel 4: Viterbi (1 warp, bp in smem) -------------------
__global__ void viterbi_k(const float* __restrict__ trans, float* __restrict__ out,
                          int out_size)
{
    extern __shared__ unsigned char bp[];      // T_SEQ * TAGS bytes
    __shared__ float trs[TAGS * 25];           // padded rows
    __shared__ float stopr[TAGS];

    const int lane = threadIdx.x;              // 0..31
    for (int i = lane; i < TAGS * TAGS; i += 32) {
        int n = i / TAGS, p = i % TAGS;
        trs[n * 25 + p] = trans[i];
    }
    if (lane < TAGS) stopr[lane] = trans[STOP_T * TAGS + lane];
    __syncwarp();

    float fv = (lane == START_T) ? 0.f : NEGV;
    float feat = (lane < TAGS) ? g_feats[lane] : 0.f;

    for (int t = 0; t < T_SEQ; t++) {
        float nf = (lane < TAGS && t + 1 < T_SEQ) ? g_feats[(t + 1) * TAGS + lane] : 0.f;
        float best = -3.4e38f;
        int bi = 0;
#pragma unroll
        for (int p = 0; p < TAGS; p++) {
            float src = __shfl_sync(0xffffffffu, fv, p);
            float v = src + ((lane < TAGS) ? trs[lane * 25 + p] : 0.f);
            if (v > best) { best = v; bi = p; }   // strict > keeps first max (jnp.argmax)
        }
        if (lane < TAGS) {
            fv = best + feat;
            bp[t * TAGS + lane] = (unsigned char)bi;
        } else {
            fv = NEGV;
        }
        feat = nf;
    }

    float ttl = (lane < TAGS) ? fv + stopr[lane] : -3.4e38f;
    float bv = ttl; int bi = lane;
#pragma unroll
    for (int o = 16; o; o >>= 1) {
        float ov = __shfl_down_sync(0xffffffffu, bv, o);
        int   oi = __shfl_down_sync(0xffffffffu, bi, o);
        if (ov > bv || (ov == bv && oi < bi)) { bv = ov; bi = oi; }
    }

    if (lane == 0) {
        float score = bv;
        int cur = bi;
        if (out_size >= T_SEQ + 1) {
            out[0] = score;
            float* path = out + 1;
            path[T_SEQ - 1] = (float)cur;
            for (int t = T_SEQ - 1; t >= 1; t--) {
                cur = bp[t * TAGS + cur];
                path[t - 1] = (float)cur;
            }
        } else if (out_size == T_SEQ) {
            out[T_SEQ - 1] = (float)cur;
            for (int t = T_SEQ - 1; t >= 1; t--) {
                cur = bp[t * TAGS + cur];
                out[t - 1] = (float)cur;
            }
        } else {
            out[0] = score;
        }
    }
}

// ---------------- launcher --------------------------------------------------
extern "C" void kernel_launch(void* const* d_in, const int* in_sizes, int n_in,
                              void* d_out, int out_size)
{
    const int*   sent  = (const int*)  d_in[0];
    const float* emb   = (const float*)d_in[1];
    const float* wihf  = (const float*)d_in[2];
    const float* whhf  = (const float*)d_in[3];
    const float* bihf  = (const float*)d_in[4];
    const float* bhhf  = (const float*)d_in[5];
    const float* wihb  = (const float*)d_in[6];
    const float* whhb  = (const float*)d_in[7];
    const float* bihb  = (const float*)d_in[8];
    const float* bhhb  = (const float*)d_in[9];
    const float* wtag  = (const float*)d_in[10];
    const float* btag  = (const float*)d_in[11];
    const float* trans = (const float*)d_in[12];
    const float* h0    = (const float*)d_in[13];
    const float* c0    = (const float*)d_in[14];
    float* out = (float*)d_out;

    proj_gemm<<<dim3(64, 64), 256>>>(sent, emb, wihf, wihb, bihf, bhhf, bihb, bhhb);
    lstm_rec<<<2 * NCTA_DIR, REC_THREADS>>>(whhf, whhb, h0, c0);
    feats_k<<<T_SEQ, 256>>>(wtag, btag);

    cudaFuncSetAttribute(viterbi_k, cudaFuncAttributeMaxDynamicSharedMemorySize,
                         T_SEQ * TAGS);
    viterbi_k<<<1, 32, T_SEQ * TAGS>>>(trans, out, out_size);
}

// round 7
// speedup vs baseline: 1.8697x; 1.8697x over previous
#include <cuda_runtime.h>
#include <cstdint>
#include <cmath>

#define T_SEQ   4096
#define TAGS    24
#define START_T 22
#define STOP_T  23
#define NEGV    (-10000.0f)

#define NCTA_DIR    64
#define REC_THREADS 256

// ---------------- scratch (device globals; no cudaMalloc allowed) ----------
__device__ float    g_xg[(size_t)T_SEQ * 4096];   // [t][dir*2048 + gate*512 + cell]
__device__ float    g_lstm[(size_t)T_SEQ * 1024]; // [t][dir*512 + cell]
__device__ float    g_feats[T_SEQ * TAGS];
__device__ float    g_h[2][2][512];               // [dir][parity][cell]
__device__ unsigned g_cnt[64];                    // [d*32] : 128B-separated counters

__device__ __forceinline__ unsigned ld_acq(const unsigned* p)
{
    unsigned v;
    asm volatile("ld.acquire.gpu.global.u32 %0, [%1];" : "=r"(v) : "l"(p) : "memory");
    return v;
}
__device__ __forceinline__ void red_rel(unsigned* p)
{
    asm volatile("red.release.gpu.global.add.u32 [%0], %1;" :: "l"(p), "r"(1u) : "memory");
}

// ---------------- kernel 1: fused gather + input-projection GEMM -----------
__global__ void proj_gemm(const int* __restrict__ sent, const float* __restrict__ emb,
                          const float* __restrict__ wf, const float* __restrict__ wb,
                          const float* __restrict__ bihf, const float* __restrict__ bhhf,
                          const float* __restrict__ bihb, const float* __restrict__ bhhb)
{
    __shared__ __align__(16) float As[32][68];
    __shared__ __align__(16) float Bs[32][68];
    __shared__ int toks[64];

    const int tid = threadIdx.x;          // 0..255
    const int m0 = blockIdx.y * 64;
    const int n0 = blockIdx.x * 64;
    if (tid < 64) toks[tid] = sent[m0 + tid];
    __syncthreads();

    const int ty = tid >> 4;              // 0..15
    const int tx = tid & 15;              // 0..15

    float acc[4][4];
#pragma unroll
    for (int i = 0; i < 4; i++)
#pragma unroll
        for (int j = 0; j < 4; j++) acc[i][j] = 0.f;

    for (int k0 = 0; k0 < 512; k0 += 32) {
#pragma unroll
        for (int r = 0; r < 2; r++) {
            int idx = tid + r * 256;
            int row = idx >> 3;
            int kq  = idx & 7;
            float4 a = *(const float4*)(emb + (size_t)toks[row] * 512 + k0 + kq * 4);
            As[kq*4+0][row] = a.x; As[kq*4+1][row] = a.y;
            As[kq*4+2][row] = a.z; As[kq*4+3][row] = a.w;
            int n = n0 + row;
            const float* wsrc = (n < 2048) ? (wf + (size_t)n * 512)
                                           : (wb + (size_t)(n - 2048) * 512);
            float4 b = *(const float4*)(wsrc + k0 + kq * 4);
            Bs[kq*4+0][row] = b.x; Bs[kq*4+1][row] = b.y;
            Bs[kq*4+2][row] = b.z; Bs[kq*4+3][row] = b.w;
        }
        __syncthreads();
#pragma unroll
        for (int kk = 0; kk < 32; kk++) {
            float4 aa = *(const float4*)&As[kk][ty * 4];
            float4 bb = *(const float4*)&Bs[kk][tx * 4];
            float av[4] = {aa.x, aa.y, aa.z, aa.w};
            float bv[4] = {bb.x, bb.y, bb.z, bb.w};
#pragma unroll
            for (int i = 0; i < 4; i++)
#pragma unroll
                for (int j = 0; j < 4; j++) acc[i][j] += av[i] * bv[j];
        }
        __syncthreads();
    }

#pragma unroll
    for (int i = 0; i < 4; i++) {
        int m = m0 + ty * 4 + i;
        float* orow = g_xg + (size_t)m * 4096 + n0 + tx * 4;
#pragma unroll
        for (int j = 0; j < 4; j++) {
            int n = n0 + tx * 4 + j;
            float bias = (n < 2048) ? (bihf[n] + bhhf[n])
                                    : (bihb[n - 2048] + bhhb[n - 2048]);
            orow[j] = acc[i][j] + bias;
        }
    }
}

// ---------------- kernel 2: persistent BiLSTM recurrence -------------------
// 128 CTAs (64/dir), 256 threads. Thread (w=tid>>5, l=tid&31):
//   row = (l>>3)*512 + 8r + (l&7), k-slice [64w, 64w+64), weights in REGISTERS.
// h published per step via one-sided counter (red.release / ld.acquire).
__global__ void __launch_bounds__(REC_THREADS, 1)
lstm_rec(const float* __restrict__ whf, const float* __restrict__ whb,
         const float* __restrict__ h0, const float* __restrict__ c0)
{
    const int cta = blockIdx.x;       // 0..127
    const int d   = cta >> 6;
    const int r   = cta & 63;         // cells [8r, 8r+8)
    const int tid = threadIdx.x;
    const int w   = tid >> 5;         // 0..7 k-slice (warp-uniform)
    const int l   = tid & 31;         // 0..31 local gate-row
    const int gate = l >> 3;
    const int cell = (r << 3) + (l & 7);
    const int row  = gate * 512 + cell;

    const float* whh = d ? whb : whf;
    unsigned* cnt = &g_cnt[d * 32];

    // ---- weights -> registers (one-time) ----
    float4 W[16];
    {
        const float4* wp = (const float4*)(whh + (size_t)row * 512 + w * 64);
#pragma unroll
        for (int i = 0; i < 16; i++) W[i] = wp[i];
    }

    __shared__ __align__(16) float sg[8][33];   // [w][l] partials, padded

    float cst = 0.f;
    if (tid < 8) {
        cst = c0[d * 512 + (r << 3) + tid];
        __stcg(&g_h[d][0][(r << 3) + tid], h0[d * 512 + (r << 3) + tid]);
    }
    __syncthreads();
    if (tid == 0) red_rel(cnt);       // publication p=0 (h0)

    unsigned target = NCTA_DIR;
    for (int s = 0; s < T_SEQ; s++) {
        const int t = d ? (T_SEQ - 1 - s) : s;

        // prefetch xg for the reducer lanes (independent of h)
        float xv = 0.f;
        if (tid < 32) xv = __ldcg(&g_xg[(size_t)t * 4096 + d * 2048 + row]);

        if (tid == 0) {
            while (ld_acq(cnt) < target) { }
        }
        __syncthreads();

        // h vector (lane-invariant addresses -> broadcast wavefronts), L2 path
        const float4* hb = (const float4*)(&g_h[d][s & 1][0]) + w * 16;
        float4 acc = {0.f, 0.f, 0.f, 0.f};
#pragma unroll
        for (int i = 0; i < 16; i++) {
            float4 h = __ldcg(hb + i);
            acc.x += W[i].x * h.x; acc.y += W[i].y * h.y;
            acc.z += W[i].z * h.z; acc.w += W[i].w * h.w;
        }
        sg[w][l] = (acc.x + acc.y) + (acc.z + acc.w);
        __syncthreads();

        if (tid < 32) {   // warp 0 reduces + gates
            float a = ((sg[0][l] + sg[1][l]) + (sg[2][l] + sg[3][l]))
                    + ((sg[4][l] + sg[5][l]) + (sg[6][l] + sg[7][l]));
            a += xv;
            float fg = __shfl_sync(0xffffffffu, a, (l & 7) + 8);
            float gg = __shfl_sync(0xffffffffu, a, (l & 7) + 16);
            float ov = __shfl_sync(0xffffffffu, a, (l & 7) + 24);
            if (l < 8) {
                float iv = 1.f / (1.f + expf(-a));
                fg = 1.f / (1.f + expf(-fg));
                gg = tanhf(gg);
                ov = 1.f / (1.f + expf(-ov));
                cst = fg * cst + iv * gg;
                float hn = ov * tanhf(cst);
                __stcg(&g_h[d][(s + 1) & 1][(r << 3) + l], hn);
                __stcg(&g_lstm[(size_t)t * 1024 + d * 512 + (r << 3) + l], hn);
            }
        }
        __syncthreads();
        if (tid == 0) red_rel(cnt);   // publication p=s+1
        target += NCTA_DIR;
    }

    // self-reset for graph replay: wait for all publications, then zero.
    if (r == 0 && tid == 0) {
        const unsigned done = (unsigned)NCTA_DIR * (T_SEQ + 1);
        while (ld_acq(cnt) < done) { }
        atomicExch(cnt, 0u);
    }
}

// ---------------- kernel 3: tag features -----------------------------------
__global__ void feats_k(const float* __restrict__ wtag, const float* __restrict__ btag)
{
    const int t = blockIdx.x;
    const int w = threadIdx.x >> 5;
    const int lane = threadIdx.x & 31;

    const float4* lx = (const float4*)(g_lstm + (size_t)t * 1024 + lane * 32);
    float4 X[8];
#pragma unroll
    for (int i = 0; i < 8; i++) X[i] = lx[i];

#pragma unroll
    for (int rep = 0; rep < 3; rep++) {
        int tag = w + rep * 8;
        const float4* wt = (const float4*)(wtag + (size_t)tag * 1024 + lane * 32);
        float a = 0.f;
#pragma unroll
        for (int i = 0; i < 8; i++) {
            float4 v = wt[i];
            a += X[i].x * v.x + X[i].y * v.y + X[i].z * v.z + X[i].w * v.w;
        }
#pragma unroll
        for (int o = 16; o; o >>= 1) a += __shfl_xor_sync(0xffffffffu, a, o);
        if (lane == 0) g_feats[t * TAGS + tag] = a + btag[tag];
    }
}

// ---------------- kernel 4: Viterbi (1 warp, bp in smem) -------------------
__global__ void viterbi_k(const float* __restrict__ trans, float* __restrict__ out,
                          int out_size)
{
    extern __shared__ unsigned char bp[];      // T_SEQ * TAGS bytes
    __shared__ float trs[TAGS * 25];
    __shared__ float stopr[TAGS];

    const int lane = threadIdx.x;
    for (int i = lane; i < TAGS * TAGS; i += 32) {
        int n = i / TAGS, p = i % TAGS;
        trs[n * 25 + p] = trans[i];
    }
    if (lane < TAGS) stopr[lane] = trans[STOP_T * TAGS + lane];
    __syncwarp();

    float fv = (lane == START_T) ? 0.f : NEGV;
    float feat = (lane < TAGS) ? g_feats[lane] : 0.f;

    for (int t = 0; t < T_SEQ; t++) {
        float nf = (lane < TAGS && t + 1 < T_SEQ) ? g_feats[(t + 1) * TAGS + lane] : 0.f;
        float best = -3.4e38f;
        int bi = 0;
#pragma unroll
        for (int p = 0; p < TAGS; p++) {
            float src = __shfl_sync(0xffffffffu, fv, p);
            float v = src + ((lane < TAGS) ? trs[lane * 25 + p] : 0.f);
            if (v > best) { best = v; bi = p; }
        }
        if (lane < TAGS) {
            fv = best + feat;
            bp[t * TAGS + lane] = (unsigned char)bi;
        } else {
            fv = NEGV;
        }
        feat = nf;
    }

    float ttl = (lane < TAGS) ? fv + stopr[lane] : -3.4e38f;
    float bv = ttl; int bi = lane;
#pragma unroll
    for (int o = 16; o; o >>= 1) {
        float ov = __shfl_down_sync(0xffffffffu, bv, o);
        int   oi = __shfl_down_sync(0xffffffffu, bi, o);
        if (ov > bv || (ov == bv && oi < bi)) { bv = ov; bi = oi; }
    }

    if (lane == 0) {
        float score = bv;
        int cur = bi;
        if (out_size >= T_SEQ + 1) {
            out[0] = score;
            float* path = out + 1;
            path[T_SEQ - 1] = (float)cur;
            for (int t = T_SEQ - 1; t >= 1; t--) {
                cur = bp[t * TAGS + cur];
                path[t - 1] = (float)cur;
            }
        } else if (out_size == T_SEQ) {
            out[T_SEQ - 1] = (float)cur;
            for (int t = T_SEQ - 1; t >= 1; t--) {
                cur = bp[t * TAGS + cur];
                out[t - 1] = (float)cur;
            }
        } else {
            out[0] = score;
        }
    }
}

// ---------------- launcher --------------------------------------------------
extern "C" void kernel_launch(void* const* d_in, const int* in_sizes, int n_in,
                              void* d_out, int out_size)
{
    const int*   sent  = (const int*)  d_in[0];
    const float* emb   = (const float*)d_in[1];
    const float* wihf  = (const float*)d_in[2];
    const float* whhf  = (const float*)d_in[3];
    const float* bihf  = (const float*)d_in[4];
    const float* bhhf  = (const float*)d_in[5];
    const float* wihb  = (const float*)d_in[6];
    const float* whhb  = (const float*)d_in[7];
    const float* bihb  = (const float*)d_in[8];
    const float* bhhb  = (const float*)d_in[9];
    const float* wtag  = (const float*)d_in[10];
    const float* btag  = (const float*)d_in[11];
    const float* trans = (const float*)d_in[12];
    const float* h0    = (const float*)d_in[13];
    const float* c0    = (const float*)d_in[14];
    float* out = (float*)d_out;

    proj_gemm<<<dim3(64, 64), 256>>>(sent, emb, wihf, wihb, bihf, bhhf, bihb, bhhb);
    lstm_rec<<<2 * NCTA_DIR, REC_THREADS>>>(whhf, whhb, h0, c0);
    feats_k<<<T_SEQ, 256>>>(wtag, btag);

    cudaFuncSetAttribute(viterbi_k, cudaFuncAttributeMaxDynamicSharedMemorySize,
                         T_SEQ * TAGS);
    viterbi_k<<<1, 32, T_SEQ * TAGS>>>(trans, out, out_size);
}